// round 10
// baseline (speedup 1.0000x reference)
#include <cuda_runtime.h>
#include <math.h>

#define SUB1 15
#define T_MAX 120000

// ---------------- scratch (device globals — no allocs allowed) ----------------
__device__ float  g_syn_e[SUB1 * T_MAX];  // [s][t]
__device__ float  g_syn_i[SUB1 * T_MAX];  // [s][t]
__device__ float2 g_wei[SUB1 * 105];      // {ke[d], ki[d]}
__device__ float2 g_whz[SUB1 * 105];      // {kh[d], ko[d]}        (obs taps 0..103)
__device__ float  g_kohi[SUB1 * 105];     // ko[104+d]             (obs taps 104..207)

// ---------------- basis functions (fp32, MUFU-fast) ----------------
__device__ __forceinline__ float cos_basis_f(int b, int d) {
    const float PI_F = 3.14159265358979f;
    float raw = 5.0f * logf((float)d + 1.0f + 1e-8f);
    float phi = 1.5707963267948966f * (float)b;
    if (raw < phi - PI_F || raw > phi + PI_F) return 0.f;
    return 0.5f * cosf(raw - phi) + 0.5f;
}

__device__ __forceinline__ float obs_basis_f(int b, int x) {
    const float PI_F = 3.14159265358979f;
    float phi;
    if (b == 0) {
        phi = 0.f;
    } else if (b & 1) {           // positive-side basis (x >= 0)
        if (x < 0) return 0.f;
        phi = 1.5707963267948966f * (float)((b + 1) >> 1);
    } else {                      // negative-side basis (x <= 0)
        if (x > 0) return 0.f;
        phi = 1.5707963267948966f * (float)(b >> 1);
    }
    float r = 5.0f * logf(fabsf((float)x) + 1.0f + 1e-8f);
    if (r < phi - PI_F || r > phi + PI_F) return 0.f;
    return 0.5f * cosf(r - phi) + 0.5f;
}

// ---------------- kernel precompute (tiny, fp32) ----------------
__global__ void prep_kernel(const float* __restrict__ W_syn,
                            const float* __restrict__ W_hist,
                            const float* __restrict__ W_obs) {
    int idx = blockIdx.x * blockDim.x + threadIdx.x;
    if (idx >= SUB1 * 105) return;
    int s = idx / 105, d = idx % 105;
    float ke = 0.f, ki = 0.f, kh = 0.f, ko = 0.f, ko2 = 0.f;
    if (d < 100) {
        for (int b = 0; b < 13; b++) {
            float bf = cos_basis_f(b, d);
            ke = fmaf(W_syn[(s * 13 + b) * 2 + 0], bf, ke);
            ki = fmaf(W_syn[(s * 13 + b) * 2 + 1], bf, ki);
            kh = fmaf(W_hist[s * 13 + b], bf, kh);
        }
    }
    if (d < 104) {  // obs tap j = d, x = j - 100
        for (int b = 0; b < 25; b++)
            ko = fmaf(W_obs[s * 25 + b], obs_basis_f(b, d - 100), ko);
    }
    if (d <= 96) {  // obs tap j = 104 + d, x = d + 4  (j <= 200)
        for (int b = 0; b < 25; b++)
            ko2 = fmaf(W_obs[s * 25 + b], obs_basis_f(b, d + 4), ko2);
    }
    g_wei[idx]  = make_float2(ke, ki);
    g_whz[idx]  = make_float2(kh, ko);
    g_kohi[idx] = ko2;
}

// ---------------- fused matmul: out[s][t] = sum_k S[t,k] * C[s+1,k] ----------------
// Row-pair f32x2 packing, transposed tile, register-staged double buffering.
// 128 threads, 4 rows/thread (pairs tid and tid+128), 512 rows/block.
// Blocks [0, nblk_e) do the E matmul (K=800); the rest do I (K=200).
#define MM_LOAD_CHUNK(k0)                                                          \
    do {                                                                           \
        _Pragma("unroll")                                                          \
        for (int it = 0; it < 8; it++) {                                           \
            int f = it * 128 + tid;                                                \
            int r = f >> 1, q = f & 1;                                             \
            int row = row0 + r;                                                    \
            float4 v = make_float4(0.f, 0.f, 0.f, 0.f);                            \
            if (row < T) v = *(const float4*)(S + (size_t)row * K + (k0) + 4 * q); \
            xs[it] = v;                                                            \
        }                                                                          \
        wv = 0.f;                                                                  \
        if (tid < 120) wv = C[(size_t)(tid % 15 + 1) * K + (k0) + tid / 15];       \
    } while (0)

__global__ __launch_bounds__(128, 4) void mm_kernel(
    const float* __restrict__ Se, const float* __restrict__ Si,
    const float* __restrict__ Ce, const float* __restrict__ Ci,
    float* __restrict__ oe, float* __restrict__ oi,
    int T, int nblk_e)
{
    __shared__ float tile[8 * 514];                 // [k][row], transposed
    __shared__ __align__(16) float2 wbuf[8 * 16];   // [k][s] duplicated {w,w}

    const bool is_e = (int)blockIdx.x < nblk_e;
    const float* S = is_e ? Se : Si;
    const float* C = is_e ? Ce : Ci;
    float* out = is_e ? oe : oi;
    const int K = is_e ? 800 : 200;
    const int blk = is_e ? blockIdx.x : blockIdx.x - nblk_e;
    const int row0 = blk * 512;
    const int tid = threadIdx.x;

    unsigned long long acc[30];   // acc[s*2 + rp]
#pragma unroll
    for (int i = 0; i < 30; i++) acc[i] = 0ull;

    float4 xs[8];
    float wv;
    MM_LOAD_CHUNK(0);

    const int nch = K >> 3;
    for (int c = 0; c < nch; c++) {
        __syncthreads();   // previous compute finished
#pragma unroll
        for (int it = 0; it < 8; it++) {
            int f = it * 128 + tid;
            int r = f >> 1, q = f & 1;
            float4 v = xs[it];
            tile[(4 * q + 0) * 514 + r] = v.x;
            tile[(4 * q + 1) * 514 + r] = v.y;
            tile[(4 * q + 2) * 514 + r] = v.z;
            tile[(4 * q + 3) * 514 + r] = v.w;
        }
        if (tid < 120) wbuf[(tid / 15) * 16 + (tid % 15)] = make_float2(wv, wv);
        __syncthreads();
        if (c + 1 < nch) MM_LOAD_CHUNK((c + 1) * 8);
#pragma unroll
        for (int k = 0; k < 8; k++) {
            unsigned long long x0 = *(const unsigned long long*)(tile + k * 514 + 2 * tid);
            unsigned long long x1 = *(const unsigned long long*)(tile + k * 514 + 2 * tid + 256);
            const ulonglong2* wp = (const ulonglong2*)(wbuf + k * 16);
#pragma unroll
            for (int p = 0; p < 7; p++) {
                ulonglong2 w01 = wp[p];   // LDS.128 broadcast: {w_{2p},w_{2p}},{w_{2p+1},w_{2p+1}}
                asm("fma.rn.f32x2 %0, %1, %2, %0;" : "+l"(acc[4 * p + 0]) : "l"(x0), "l"(w01.x));
                asm("fma.rn.f32x2 %0, %1, %2, %0;" : "+l"(acc[4 * p + 1]) : "l"(x1), "l"(w01.x));
                asm("fma.rn.f32x2 %0, %1, %2, %0;" : "+l"(acc[4 * p + 2]) : "l"(x0), "l"(w01.y));
                asm("fma.rn.f32x2 %0, %1, %2, %0;" : "+l"(acc[4 * p + 3]) : "l"(x1), "l"(w01.y));
            }
            unsigned long long w14 = *(const unsigned long long*)(wbuf + k * 16 + 14);
            asm("fma.rn.f32x2 %0, %1, %2, %0;" : "+l"(acc[28]) : "l"(x0), "l"(w14));
            asm("fma.rn.f32x2 %0, %1, %2, %0;" : "+l"(acc[29]) : "l"(x1), "l"(w14));
        }
    }

    // acc pairs are adjacent t in [s][t] layout -> direct coalesced STG.64
    const int ra = row0 + 2 * tid;         // rows 2tid, 2tid+1
    const int rb = row0 + 2 * tid + 256;   // rows of pair tid+128
#pragma unroll
    for (int s = 0; s < SUB1; s++) {
        if (ra < T) *(unsigned long long*)(out + (size_t)s * T + ra) = acc[s * 2 + 0];
        if (rb < T) *(unsigned long long*)(out + (size_t)s * T + rb) = acc[s * 2 + 1];
    }
}

// ---------------- fused sliding-window conv, weights software-pipelined ----------------
__device__ __forceinline__ void conv_fused(unsigned long long acc2[8], float accs[8],
                                           const float2* __restrict__ sei,
                                           const float2* __restrict__ wei,
                                           const float2* __restrict__ hz,
                                           const float2* __restrict__ whz,
                                           const float* __restrict__ zo,
                                           const float* __restrict__ koh,
                                           int base_a, int base_b, int base_c) {
    unsigned long long ya[8], yb[8];
    float yc[8];
#pragma unroll
    for (int j = 0; j < 8; j++) {
        ya[j] = *(const unsigned long long*)(sei + (base_a + j) * 17);
        yb[j] = *(const unsigned long long*)(hz + (base_b + j) * 17);
        yc[j] = zo[base_c + j];
    }
    unsigned long long wa = *(const unsigned long long*)(wei);
    unsigned long long wb = *(const unsigned long long*)(whz);
    float wc = koh[0];
#pragma unroll 1
    for (int d0 = 0; d0 < 104; d0 += 8) {
#pragma unroll
        for (int dd = 0; dd < 8; dd++) {
            int d = d0 + dd;
            // prefetch next-tap weights (d+1 <= 104, in bounds)
            unsigned long long wa_n = *(const unsigned long long*)(wei + d + 1);
            unsigned long long wb_n = *(const unsigned long long*)(whz + d + 1);
            float wc_n = koh[d + 1];
#pragma unroll
            for (int r = 0; r < 8; r++)
                asm("fma.rn.f32x2 %0, %1, %2, %0;" : "+l"(acc2[r]) : "l"(ya[(r - dd) & 7]), "l"(wa));
#pragma unroll
            for (int r = 0; r < 8; r++)
                asm("fma.rn.f32x2 %0, %1, %2, %0;" : "+l"(acc2[r]) : "l"(yb[(r - dd) & 7]), "l"(wb));
#pragma unroll
            for (int r = 0; r < 8; r++)
                accs[r] = fmaf(yc[(r - dd) & 7], wc, accs[r]);
            ya[(7 - dd) & 7] = *(const unsigned long long*)(sei + (base_a - d - 1) * 17);
            yb[(7 - dd) & 7] = *(const unsigned long long*)(hz + (base_b - d - 1) * 17);
            yc[(7 - dd) & 7] = zo[base_c - d - 1];
            wa = wa_n; wb = wb_n; wc = wc_n;
        }
    }
}

// out[t,s] = exp( conv_ei + conv_hist + conv_obs + Theta[s] )
__global__ __launch_bounds__(256, 2) void conv_kernel(const float* __restrict__ Z_obs,
                                                      const float* __restrict__ Z_hid,
                                                      const float* __restrict__ Theta,
                                                      float* __restrict__ out0,
                                                      float* __restrict__ out1,
                                                      int T) {
    extern __shared__ float sm[];
    float2* sei = (float2*)sm;             // [232][17]  {syn_e, syn_i}, origin t0-104
    float2* hz  = sei + 232 * 17;          // [232][17]  {Z_hid[u], Z_obs[u+101]}, origin t0-104
    float*  zo  = (float*)(hz + 232 * 17); // [232]      Z_obs, origin t0-108
    float2* wei = (float2*)(zo + 232);     // [15][105]  {ke, ki}
    float2* whz = wei + SUB1 * 105;        // [15][105]  {kh, ko_lo}
    float*  koh = (float*)(whz + SUB1 * 105); // [15*105] ko_hi
    const int tid = threadIdx.x;
    const int t0 = blockIdx.x * 128;

    // signals from [s][t] matmul outputs: coalesced per-s rows
#pragma unroll 1
    for (int s2 = 0; s2 < SUB1; s2++) {
        for (int lt = tid; lt < 232; lt += 256) {
            int t = t0 - 104 + lt;
            float ve = 0.f, vi2 = 0.f;
            if (t >= 0 && t < T) {
                ve  = g_syn_e[(size_t)s2 * T + t];
                vi2 = g_syn_i[(size_t)s2 * T + t];
            }
            sei[lt * 17 + s2] = make_float2(ve, vi2);
        }
    }
    for (int li = tid; li < 232 * 16; li += 256) {
        int lt = li >> 4, s = li & 15;
        int t = t0 - 104 + lt;
        float zh = (s < SUB1 && t >= 0 && t < T) ? Z_hid[(size_t)t * SUB1 + s] : 0.f;
        int uz = t + 101;
        float zb = (uz >= 0 && uz < T) ? Z_obs[uz] : 0.f;
        hz[lt * 17 + s] = make_float2(zh, zb);
    }
    for (int li = tid; li < 232; li += 256) {
        int t = t0 - 108 + li;
        zo[li] = (t >= 0 && t < T) ? Z_obs[t] : 0.f;
    }
    for (int li = tid; li < SUB1 * 105; li += 256) {
        wei[li] = g_wei[li];
        whz[li] = g_whz[li];
        koh[li] = g_kohi[li];
    }
    __syncthreads();

    const int s = tid & 15;
    const int trun = tid >> 4;
    if (s >= SUB1) return;   // no barriers after this point

    unsigned long long acc2[8];
#pragma unroll
    for (int r = 0; r < 8; r++) acc2[r] = 0ull;
    float accs[8];
    float th = __ldg(Theta + s);
#pragma unroll
    for (int r = 0; r < 8; r++) accs[r] = th;

    conv_fused(acc2, accs,
               sei + s, wei + s * 105,
               hz + s, whz + s * 105,
               zo, koh + s * 105,
               104 + trun * 8,    // ei:   sum_d {syn_e,syn_i}[t-d] * {ke,ki}[d]
               103 + trun * 8,    // hz:   sum_d {Z_hid[t-1-d], Z_obs[t+100-d]} * {kh,ko}[d]
               104 + trun * 8);   // obs:  sum_d Z_obs[t-4-d] * ko[104+d]

    const int tb = t0 + trun * 8;
#pragma unroll
    for (int r = 0; r < 8; r++) {
        int t = tb + r;
        if (t < T) {
            float lo, hi;
            asm("mov.b64 {%0,%1}, %2;" : "=f"(lo), "=f"(hi) : "l"(acc2[r]));
            float v = expf(lo + hi + accs[r]);
            out0[(size_t)t * SUB1 + s] = v;
            out1[(size_t)t * SUB1 + s] = v;
        }
    }
}

extern "C" void kernel_launch(void* const* d_in, const int* in_sizes, int n_in,
                              void* d_out, int out_size) {
    const float* S_e    = (const float*)d_in[0];
    const float* S_i    = (const float*)d_in[1];
    const float* Z_obs  = (const float*)d_in[2];
    const float* Z_hid  = (const float*)d_in[3];
    const float* C_e    = (const float*)d_in[4];
    const float* C_i    = (const float*)d_in[5];
    const float* W_syn  = (const float*)d_in[6];
    const float* W_hist = (const float*)d_in[7];
    const float* W_obs  = (const float*)d_in[8];
    const float* Theta  = (const float*)d_in[9];
    const int T = in_sizes[2];          // Z_obs element count

    float* out0 = (float*)d_out;
    float* out1 = (out_size >= 2 * T * SUB1) ? out0 + (size_t)T * SUB1 : out0;

    const int smem_conv = (2 * 232 * 17 * 2 + 232 + 2 * SUB1 * 105 * 2 + SUB1 * 105) * (int)sizeof(float); // 95,532
    cudaFuncSetAttribute(conv_kernel, cudaFuncAttributeMaxDynamicSharedMemorySize, smem_conv);

    float* syn_e_ptr; float* syn_i_ptr;
    cudaGetSymbolAddress((void**)&syn_e_ptr, g_syn_e);
    cudaGetSymbolAddress((void**)&syn_i_ptr, g_syn_i);

    prep_kernel<<<(SUB1 * 105 + 255) / 256, 256>>>(W_syn, W_hist, W_obs);

    int nblk = (T + 511) / 512;
    mm_kernel<<<2 * nblk, 128>>>(S_e, S_i, C_e, C_i, syn_e_ptr, syn_i_ptr, T, nblk);

    int conv_blocks = (T + 127) / 128;
    conv_kernel<<<conv_blocks, 256, smem_conv>>>(Z_obs, Z_hid, Theta, out0, out1, T);
}

// round 12
// speedup vs baseline: 1.3833x; 1.3833x over previous
#include <cuda_runtime.h>
#include <math.h>

#define SUB1 15
#define T_MAX 120000

// ---------------- scratch (device globals — no allocs allowed) ----------------
__device__ float  g_syn[T_MAX * 32];      // interleaved {e,i} per (t,s): [t][s][2], s-pitch 32
__device__ float2 g_wei[SUB1 * 105];      // {ke[d], ki[d]}
__device__ float2 g_whz[SUB1 * 105];      // {kh[d], ko[d]}        (obs taps 0..103)
__device__ float  g_kohi[SUB1 * 105];     // ko[104+d]             (obs taps 104..207)

// ---------------- basis functions (fp32, MUFU-fast) ----------------
__device__ __forceinline__ float cos_basis_f(int b, int d) {
    const float PI_F = 3.14159265358979f;
    float raw = 5.0f * logf((float)d + 1.0f + 1e-8f);
    float phi = 1.5707963267948966f * (float)b;
    if (raw < phi - PI_F || raw > phi + PI_F) return 0.f;
    return 0.5f * cosf(raw - phi) + 0.5f;
}

__device__ __forceinline__ float obs_basis_f(int b, int x) {
    const float PI_F = 3.14159265358979f;
    float phi;
    if (b == 0) {
        phi = 0.f;
    } else if (b & 1) {           // positive-side basis (x >= 0)
        if (x < 0) return 0.f;
        phi = 1.5707963267948966f * (float)((b + 1) >> 1);
    } else {                      // negative-side basis (x <= 0)
        if (x > 0) return 0.f;
        phi = 1.5707963267948966f * (float)(b >> 1);
    }
    float r = 5.0f * logf(fabsf((float)x) + 1.0f + 1e-8f);
    if (r < phi - PI_F || r > phi + PI_F) return 0.f;
    return 0.5f * cosf(r - phi) + 0.5f;
}

// ---------------- kernel precompute, run by the mm_e tail block ----------------
__device__ void prep_body(int tid, const float* __restrict__ W_syn,
                          const float* __restrict__ W_hist,
                          const float* __restrict__ W_obs) {
    for (int idx = tid; idx < SUB1 * 105; idx += 256) {
        int s = idx / 105, d = idx % 105;
        float ke = 0.f, ki = 0.f, kh = 0.f, ko = 0.f, ko2 = 0.f;
        if (d < 100) {
            for (int b = 0; b < 13; b++) {
                float bf = cos_basis_f(b, d);
                ke = fmaf(W_syn[(s * 13 + b) * 2 + 0], bf, ke);
                ki = fmaf(W_syn[(s * 13 + b) * 2 + 1], bf, ki);
                kh = fmaf(W_hist[s * 13 + b], bf, kh);
            }
        }
        if (d < 104) {  // obs tap j = d, x = j - 100
            for (int b = 0; b < 25; b++)
                ko = fmaf(W_obs[s * 25 + b], obs_basis_f(b, d - 100), ko);
        }
        if (d <= 96) {  // obs tap j = 104 + d, x = d + 4  (j <= 200)
            for (int b = 0; b < 25; b++)
                ko2 = fmaf(W_obs[s * 25 + b], obs_basis_f(b, d + 4), ko2);
        }
        g_wei[idx]  = make_float2(ke, ki);
        g_whz[idx]  = make_float2(kh, ko);
        g_kohi[idx] = ko2;
    }
}

// ---------------- cp.async helpers ----------------
__device__ __forceinline__ unsigned smem_u32(const void* p) {
    return (unsigned)__cvta_generic_to_shared(p);
}
__device__ __forceinline__ void cp16(unsigned dst, const float* src, int sz) {
    asm volatile("cp.async.cg.shared.global [%0], [%1], 16, %2;" :: "r"(dst), "l"(src), "r"(sz));
}
__device__ __forceinline__ void cp8(unsigned dst, const float* src) {
    asm volatile("cp.async.ca.shared.global [%0], [%1], 8;" :: "r"(dst), "l"(src));
}

// ---------------- matmul v4: out[t*32 + 2s + ch] = sum_k S[t,k] * C[s+1,k] ----------------
// k-pair f32x2 packing (v2 compute), cp.async 2-stage double buffering, LDS.128 weights.
// 256 threads, rows tid & tid+256 per thread, 512 rows/block.
template <int K, int KC, bool DO_PREP>
__global__ __launch_bounds__(256, 2) void mm_kernel(const float* __restrict__ S,
                                                    const float* __restrict__ C,
                                                    float* __restrict__ out, int T,
                                                    int ch, int nblk,
                                                    const float* Wsyn, const float* Whist,
                                                    const float* Wobs) {
    if (DO_PREP && (int)blockIdx.x == nblk) { prep_body(threadIdx.x, Wsyn, Whist, Wobs); return; }

    extern __shared__ float sm[];
    const int PITCH = KC + 4;                 // keeps every 16B cp.async dst aligned
    const int KCH = KC / 2;                   // k-pairs per chunk
    const int QR = KC / 4;                    // float4 quads per row
    float*  tile = sm;                        // [2][512*PITCH]
    float2* wbuf = (float2*)(sm + 2 * 512 * PITCH);  // [2][KCH][16]
    const int tid = threadIdx.x;
    const int row0 = (int)blockIdx.x * 512;
    const unsigned tile_s = smem_u32(tile);
    const unsigned wbuf_s = smem_u32(wbuf);

    auto issue_chunk = [&](int c) {
        const int k0 = c * KC;
        const unsigned tb = tile_s + (unsigned)((c & 1) * 512 * PITCH * 4);
#pragma unroll
        for (int it = 0; it < KC / 2; it++) {   // 512*QR copies / 256 threads
            int f = it * 256 + tid;
            int r = f / QR, q = f % QR;
            int row = row0 + r;
            int sz = (row < T) ? 16 : 0;
            const float* src = S + (size_t)(row < T ? row : T - 1) * K + k0 + 4 * q;
            cp16(tb + (unsigned)((r * PITCH + 4 * q) * 4), src, sz);
        }
        if (tid < SUB1 * KCH) {
            int s = tid / KCH, j = tid % KCH;
            cp8(wbuf_s + (unsigned)((((c & 1) * KCH + j) * 16 + s) * 8),
                C + (size_t)(s + 1) * K + k0 + 2 * j);
        }
        asm volatile("cp.async.commit_group;");
    };

    unsigned long long acc[30];   // acc[2s] row tid (k-even/odd lanes), acc[2s+1] row tid+256
#pragma unroll
    for (int i = 0; i < 30; i++) acc[i] = 0ull;

    issue_chunk(0);
    const int nch = K / KC;
    for (int c = 0; c < nch; c++) {
        if (c + 1 < nch) {
            issue_chunk(c + 1);
            asm volatile("cp.async.wait_group 1;");
        } else {
            asm volatile("cp.async.wait_group 0;");
        }
        __syncthreads();                            // chunk c visible to all
        const float* tb = tile + (c & 1) * 512 * PITCH;
        const float2* wb = wbuf + (c & 1) * KCH * 16;
#pragma unroll
        for (int j = 0; j < KCH; j++) {
            unsigned long long x0 = *(const unsigned long long*)(tb + tid * PITCH + 2 * j);
            unsigned long long x1 = *(const unsigned long long*)(tb + (tid + 256) * PITCH + 2 * j);
            const ulonglong2* wp = (const ulonglong2*)(wb + j * 16);
#pragma unroll
            for (int p = 0; p < 7; p++) {
                ulonglong2 w01 = wp[p];  // LDS.128 broadcast: w-pairs for s=2p, s=2p+1
                asm("fma.rn.f32x2 %0, %1, %2, %0;" : "+l"(acc[4 * p + 0]) : "l"(x0), "l"(w01.x));
                asm("fma.rn.f32x2 %0, %1, %2, %0;" : "+l"(acc[4 * p + 1]) : "l"(x1), "l"(w01.x));
                asm("fma.rn.f32x2 %0, %1, %2, %0;" : "+l"(acc[4 * p + 2]) : "l"(x0), "l"(w01.y));
                asm("fma.rn.f32x2 %0, %1, %2, %0;" : "+l"(acc[4 * p + 3]) : "l"(x1), "l"(w01.y));
            }
            unsigned long long w14 = *(const unsigned long long*)((const unsigned long long*)wb + j * 16 + 14);
            asm("fma.rn.f32x2 %0, %1, %2, %0;" : "+l"(acc[28]) : "l"(x0), "l"(w14));
            asm("fma.rn.f32x2 %0, %1, %2, %0;" : "+l"(acc[29]) : "l"(x1), "l"(w14));
        }
        __syncthreads();                            // all reads of this buffer done before reuse
    }

    int r0 = row0 + tid, r1 = row0 + 256 + tid;
#pragma unroll
    for (int s = 0; s < SUB1; s++) {
        float lo, hi;
        asm("mov.b64 {%0,%1}, %2;" : "=f"(lo), "=f"(hi) : "l"(acc[2 * s]));
        if (r0 < T) out[(size_t)r0 * 32 + 2 * s + ch] = lo + hi;
        asm("mov.b64 {%0,%1}, %2;" : "=f"(lo), "=f"(hi) : "l"(acc[2 * s + 1]));
        if (r1 < T) out[(size_t)r1 * 32 + 2 * s + ch] = lo + hi;
    }
}

// ---------------- fused sliding-window conv (269-us baseline, unchanged) ----------------
__device__ __forceinline__ void conv_fused(unsigned long long acc2[8], float accs[8],
                                           const float2* __restrict__ sei,
                                           const float2* __restrict__ wei,
                                           const float2* __restrict__ hz,
                                           const float2* __restrict__ whz,
                                           const float* __restrict__ zo,
                                           const float* __restrict__ koh,
                                           int base_a, int base_b, int base_c) {
    unsigned long long ya[8], yb[8];
    float yc[8];
#pragma unroll
    for (int j = 0; j < 8; j++) {
        ya[j] = *(const unsigned long long*)(sei + (base_a + j) * 17);
        yb[j] = *(const unsigned long long*)(hz + (base_b + j) * 17);
        yc[j] = zo[base_c + j];
    }
#pragma unroll 1
    for (int d0 = 0; d0 < 104; d0 += 8) {
#pragma unroll
        for (int dd = 0; dd < 8; dd++) {
            unsigned long long wa = *(const unsigned long long*)(wei + d0 + dd);
            unsigned long long wb = *(const unsigned long long*)(whz + d0 + dd);
            float wc = koh[d0 + dd];
#pragma unroll
            for (int r = 0; r < 8; r++)
                asm("fma.rn.f32x2 %0, %1, %2, %0;" : "+l"(acc2[r]) : "l"(ya[(r - dd) & 7]), "l"(wa));
#pragma unroll
            for (int r = 0; r < 8; r++)
                asm("fma.rn.f32x2 %0, %1, %2, %0;" : "+l"(acc2[r]) : "l"(yb[(r - dd) & 7]), "l"(wb));
#pragma unroll
            for (int r = 0; r < 8; r++)
                accs[r] = fmaf(yc[(r - dd) & 7], wc, accs[r]);
            ya[(7 - dd) & 7] = *(const unsigned long long*)(sei + (base_a - (d0 + dd) - 1) * 17);
            yb[(7 - dd) & 7] = *(const unsigned long long*)(hz + (base_b - (d0 + dd) - 1) * 17);
            yc[(7 - dd) & 7] = zo[base_c - (d0 + dd) - 1];
        }
    }
}

// out[t,s] = exp( conv_ei + conv_hist + conv_obs + Theta[s] )
__global__ __launch_bounds__(256, 2) void conv_kernel(const float* __restrict__ Z_obs,
                                                      const float* __restrict__ Z_hid,
                                                      const float* __restrict__ Theta,
                                                      float* __restrict__ out0,
                                                      float* __restrict__ out1,
                                                      int T) {
    extern __shared__ float sm[];
    float2* sei = (float2*)sm;             // [232][17]  {syn_e, syn_i}, origin t0-104
    float2* hz  = sei + 232 * 17;          // [232][17]  {Z_hid[u], Z_obs[u+101]}, origin t0-104
    float*  zo  = (float*)(hz + 232 * 17); // [232]      Z_obs, origin t0-108
    float2* wei = (float2*)(zo + 232);     // [15][105]  {ke, ki}
    float2* whz = wei + SUB1 * 105;        // [15][105]  {kh, ko_lo}
    float*  koh = (float*)(whz + SUB1 * 105); // [15*105] ko_hi
    const int tid = threadIdx.x;
    const int t0 = blockIdx.x * 128;

    for (int li = tid; li < 232 * 16; li += 256) {
        int lt = li >> 4, s = li & 15;
        int t = t0 - 104 + lt;
        float2 v = make_float2(0.f, 0.f);
        if (s < SUB1 && t >= 0 && t < T) v = *(const float2*)(g_syn + (size_t)t * 32 + 2 * s);
        sei[lt * 17 + s] = v;
        float zh = (s < SUB1 && t >= 0 && t < T) ? Z_hid[(size_t)t * SUB1 + s] : 0.f;
        int uz = t + 101;
        float zb = (uz >= 0 && uz < T) ? Z_obs[uz] : 0.f;
        hz[lt * 17 + s] = make_float2(zh, zb);
    }
    for (int li = tid; li < 232; li += 256) {
        int t = t0 - 108 + li;
        zo[li] = (t >= 0 && t < T) ? Z_obs[t] : 0.f;
    }
    for (int li = tid; li < SUB1 * 105; li += 256) {
        wei[li] = g_wei[li];
        whz[li] = g_whz[li];
        koh[li] = g_kohi[li];
    }
    __syncthreads();

    const int s = tid & 15;
    const int trun = tid >> 4;
    if (s >= SUB1) return;   // no barriers after this point

    unsigned long long acc2[8];
#pragma unroll
    for (int r = 0; r < 8; r++) acc2[r] = 0ull;
    float accs[8];
    float th = __ldg(Theta + s);
#pragma unroll
    for (int r = 0; r < 8; r++) accs[r] = th;

    conv_fused(acc2, accs,
               sei + s, wei + s * 105,
               hz + s, whz + s * 105,
               zo, koh + s * 105,
               104 + trun * 8,    // ei:   sum_d {syn_e,syn_i}[t-d] * {ke,ki}[d]
               103 + trun * 8,    // hz:   sum_d {Z_hid[t-1-d], Z_obs[t+100-d]} * {kh,ko}[d]
               104 + trun * 8);   // obs:  sum_d Z_obs[t-4-d] * ko[104+d]

    const int tb = t0 + trun * 8;
#pragma unroll
    for (int r = 0; r < 8; r++) {
        int t = tb + r;
        if (t < T) {
            float lo, hi;
            asm("mov.b64 {%0,%1}, %2;" : "=f"(lo), "=f"(hi) : "l"(acc2[r]));
            float v = expf(lo + hi + accs[r]);
            out0[(size_t)t * SUB1 + s] = v;
            out1[(size_t)t * SUB1 + s] = v;
        }
    }
}

extern "C" void kernel_launch(void* const* d_in, const int* in_sizes, int n_in,
                              void* d_out, int out_size) {
    const float* S_e    = (const float*)d_in[0];
    const float* S_i    = (const float*)d_in[1];
    const float* Z_obs  = (const float*)d_in[2];
    const float* Z_hid  = (const float*)d_in[3];
    const float* C_e    = (const float*)d_in[4];
    const float* C_i    = (const float*)d_in[5];
    const float* W_syn  = (const float*)d_in[6];
    const float* W_hist = (const float*)d_in[7];
    const float* W_obs  = (const float*)d_in[8];
    const float* Theta  = (const float*)d_in[9];
    const int T = in_sizes[2];          // Z_obs element count

    float* out0 = (float*)d_out;
    float* out1 = (out_size >= 2 * T * SUB1) ? out0 + (size_t)T * SUB1 : out0;

    // smem: tile 2*512*PITCH*4 + wbuf 2*KCH*16*8
    const int smem_e = 2 * 512 * 20 * 4 + 2 * 8 * 16 * 8;   // 83,968
    const int smem_i = 2 * 512 * 12 * 4 + 2 * 4 * 16 * 8;   // 50,176
    const int smem_conv = (2 * 232 * 17 * 2 + 232 + 2 * SUB1 * 105 * 2 + SUB1 * 105) * (int)sizeof(float); // 95,532

    cudaFuncSetAttribute(mm_kernel<800, 16, true>,  cudaFuncAttributeMaxDynamicSharedMemorySize, smem_e);
    cudaFuncSetAttribute(mm_kernel<200, 8, false>,  cudaFuncAttributeMaxDynamicSharedMemorySize, smem_i);
    cudaFuncSetAttribute(conv_kernel,               cudaFuncAttributeMaxDynamicSharedMemorySize, smem_conv);

    float* syn_ptr;
    cudaGetSymbolAddress((void**)&syn_ptr, g_syn);

    int nblk = (T + 511) / 512;
    // mm_e launch carries prep as its tail block (hidden under the matmul)
    mm_kernel<800, 16, true><<<nblk + 1, 256, smem_e>>>(S_e, C_e, syn_ptr, T, 0, nblk,
                                                        W_syn, W_hist, W_obs);
    mm_kernel<200, 8, false><<<nblk, 256, smem_i>>>(S_i, C_i, syn_ptr, T, 1, nblk,
                                                    W_syn, W_hist, W_obs);

    int conv_blocks = (T + 127) / 128;
    conv_kernel<<<conv_blocks, 256, smem_conv>>>(Z_obs, Z_hid, Theta, out0, out1, T);
}

// round 14
// speedup vs baseline: 1.7045x; 1.2322x over previous
#include <cuda_runtime.h>
#include <math.h>

#define SUB1 15
#define T_MAX 120000

// ---------------- scratch (device globals — no allocs allowed) ----------------
__device__ float  g_syn[T_MAX * 32];      // interleaved {e,i} per (t,s): [t][s][2], s-pitch 32
__device__ float2 g_wei[SUB1 * 105];      // {ke[d], ki[d]}
__device__ float2 g_whz[SUB1 * 105];      // {kh[d], ko[d]}        (obs taps 0..103)
__device__ float  g_kohi[SUB1 * 105];     // ko[104+d]             (obs taps 104..207)

// ---------------- basis functions (fp32, MUFU-fast) ----------------
__device__ __forceinline__ float cos_basis_f(int b, int d) {
    const float PI_F = 3.14159265358979f;
    float raw = 5.0f * logf((float)d + 1.0f + 1e-8f);
    float phi = 1.5707963267948966f * (float)b;
    if (raw < phi - PI_F || raw > phi + PI_F) return 0.f;
    return 0.5f * cosf(raw - phi) + 0.5f;
}

__device__ __forceinline__ float obs_basis_f(int b, int x) {
    const float PI_F = 3.14159265358979f;
    float phi;
    if (b == 0) {
        phi = 0.f;
    } else if (b & 1) {           // positive-side basis (x >= 0)
        if (x < 0) return 0.f;
        phi = 1.5707963267948966f * (float)((b + 1) >> 1);
    } else {                      // negative-side basis (x <= 0)
        if (x > 0) return 0.f;
        phi = 1.5707963267948966f * (float)(b >> 1);
    }
    float r = 5.0f * logf(fabsf((float)x) + 1.0f + 1e-8f);
    if (r < phi - PI_F || r > phi + PI_F) return 0.f;
    return 0.5f * cosf(r - phi) + 0.5f;
}

// ---------------- kernel precompute, run by block 0 of the fused mm launch ----------------
__device__ void prep_body(int tid, const float* __restrict__ W_syn,
                          const float* __restrict__ W_hist,
                          const float* __restrict__ W_obs) {
    for (int idx = tid; idx < SUB1 * 105; idx += 256) {
        int s = idx / 105, d = idx % 105;
        float ke = 0.f, ki = 0.f, kh = 0.f, ko = 0.f, ko2 = 0.f;
        if (d < 100) {
            for (int b = 0; b < 13; b++) {
                float bf = cos_basis_f(b, d);
                ke = fmaf(W_syn[(s * 13 + b) * 2 + 0], bf, ke);
                ki = fmaf(W_syn[(s * 13 + b) * 2 + 1], bf, ki);
                kh = fmaf(W_hist[s * 13 + b], bf, kh);
            }
        }
        if (d < 104) {  // obs tap j = d, x = j - 100
            for (int b = 0; b < 25; b++)
                ko = fmaf(W_obs[s * 25 + b], obs_basis_f(b, d - 100), ko);
        }
        if (d <= 96) {  // obs tap j = 104 + d, x = d + 4  (j <= 200)
            for (int b = 0; b < 25; b++)
                ko2 = fmaf(W_obs[s * 25 + b], obs_basis_f(b, d + 4), ko2);
        }
        g_wei[idx]  = make_float2(ke, ki);
        g_whz[idx]  = make_float2(kh, ko);
        g_kohi[idx] = ko2;
    }
}

// ---------------- cp.async helpers ----------------
__device__ __forceinline__ unsigned smem_u32(const void* p) {
    return (unsigned)__cvta_generic_to_shared(p);
}
__device__ __forceinline__ void cp16(unsigned dst, const float* src, int sz) {
    asm volatile("cp.async.cg.shared.global [%0], [%1], 16, %2;" :: "r"(dst), "l"(src), "r"(sz));
}
__device__ __forceinline__ void cp8(unsigned dst, const float* src) {
    asm volatile("cp.async.ca.shared.global [%0], [%1], 8;" :: "r"(dst), "l"(src));
}

// 30 FFMA2 for one k-pair against all 15 subunits (weights via LDS.128 broadcast)
__device__ __forceinline__ void mm_jstep(unsigned long long* acc,
                                         unsigned long long x0, unsigned long long x1,
                                         const float2* wrow) {
    const ulonglong2* wp = (const ulonglong2*)wrow;
#pragma unroll
    for (int p = 0; p < 7; p++) {
        ulonglong2 w01 = wp[p];
        asm("fma.rn.f32x2 %0, %1, %2, %0;" : "+l"(acc[4 * p + 0]) : "l"(x0), "l"(w01.x));
        asm("fma.rn.f32x2 %0, %1, %2, %0;" : "+l"(acc[4 * p + 1]) : "l"(x1), "l"(w01.x));
        asm("fma.rn.f32x2 %0, %1, %2, %0;" : "+l"(acc[4 * p + 2]) : "l"(x0), "l"(w01.y));
        asm("fma.rn.f32x2 %0, %1, %2, %0;" : "+l"(acc[4 * p + 3]) : "l"(x1), "l"(w01.y));
    }
    unsigned long long w14 = *(const unsigned long long*)((const unsigned long long*)wrow + 14);
    asm("fma.rn.f32x2 %0, %1, %2, %0;" : "+l"(acc[28]) : "l"(x0), "l"(w14));
    asm("fma.rn.f32x2 %0, %1, %2, %0;" : "+l"(acc[29]) : "l"(x1), "l"(w14));
}

// ---------------- matmul body: out[t*32 + 2s + ch] = sum_k S[t,k] * C[s+1,k] ----------------
// XOR-quad-swizzled tile (conflict-free LDS.128 x-reads), cp.async double buffering.
// 256 threads, rows tid & tid+256, 512 rows/block.
template <int K, int KC, int SWS>
__device__ __forceinline__ void mm_body(const float* __restrict__ S,
                                        const float* __restrict__ C,
                                        float* __restrict__ out, int T,
                                        int ch, int row0, float* sm) {
    const int QR = KC / 4;      // quads per row
    const int KCH = KC / 2;     // k-pairs per chunk
    float*  tile = sm;                          // [2][512*KC], quad-swizzled
    float2* wbuf = (float2*)(sm + 2 * 512 * KC);   // [2][KCH][16]
    const int tid = threadIdx.x;
    const unsigned tile_s = smem_u32(tile);
    const unsigned wbuf_s = smem_u32(wbuf);

#define MM_ISSUE(c)                                                                     \
    do {                                                                                \
        const int k0_ = (c) * KC;                                                       \
        const unsigned tb_ = tile_s + (unsigned)(((c) & 1) * 512 * KC * 4);             \
        _Pragma("unroll")                                                               \
        for (int it = 0; it < 512 * QR / 256; it++) {                                   \
            int f = it * 256 + tid;                                                     \
            int r = f / QR, q = f & (QR - 1);                                           \
            int row = row0 + r;                                                         \
            int sz = (row < T) ? 16 : 0;                                                \
            int qs = q ^ ((r >> SWS) & (QR - 1));                                       \
            cp16(tb_ + (unsigned)((r * KC + 4 * qs) * 4),                               \
                 S + (size_t)(row < T ? row : 0) * K + k0_ + 4 * q, sz);                \
        }                                                                               \
        if (tid < SUB1 * KCH) {                                                         \
            int s_ = tid / KCH, j_ = tid % KCH;                                         \
            cp8(wbuf_s + (unsigned)(((((c) & 1) * KCH + j_) * 16 + s_) * 8),            \
                C + (size_t)(s_ + 1) * K + k0_ + 2 * j_);                               \
        }                                                                               \
        asm volatile("cp.async.commit_group;");                                         \
    } while (0)

    unsigned long long acc[30];
#pragma unroll
    for (int i = 0; i < 30; i++) acc[i] = 0ull;

    const int sw0 = (tid >> SWS) & (QR - 1);   // same for rows tid and tid+256

    MM_ISSUE(0);
    const int nch = K / KC;
    for (int c = 0; c < nch; c++) {
        if (c + 1 < nch) {
            MM_ISSUE(c + 1);
            asm volatile("cp.async.wait_group 1;");
        } else {
            asm volatile("cp.async.wait_group 0;");
        }
        __syncthreads();
        const float* tb = tile + (c & 1) * 512 * KC;
        const float2* wb = wbuf + (c & 1) * KCH * 16;
#pragma unroll
        for (int q = 0; q < QR; q++) {
            int qs = q ^ sw0;
            ulonglong2 xa = *(const ulonglong2*)(tb + tid * KC + 4 * qs);
            ulonglong2 xb = *(const ulonglong2*)(tb + (tid + 256) * KC + 4 * qs);
            mm_jstep(acc, xa.x, xb.x, wb + (2 * q) * 16);
            mm_jstep(acc, xa.y, xb.y, wb + (2 * q + 1) * 16);
        }
        __syncthreads();
    }
#undef MM_ISSUE

    int r0 = row0 + tid, r1 = row0 + 256 + tid;
#pragma unroll
    for (int s = 0; s < SUB1; s++) {
        float lo, hi;
        asm("mov.b64 {%0,%1}, %2;" : "=f"(lo), "=f"(hi) : "l"(acc[2 * s]));
        if (r0 < T) out[(size_t)r0 * 32 + 2 * s + ch] = lo + hi;
        asm("mov.b64 {%0,%1}, %2;" : "=f"(lo), "=f"(hi) : "l"(acc[2 * s + 1]));
        if (r1 < T) out[(size_t)r1 * 32 + 2 * s + ch] = lo + hi;
    }
}

// Fused launch: block 0 = prep, blocks [1, nblk] = E matmul, rest = I matmul.
__global__ __launch_bounds__(256, 2) void mm_fused(
    const float* __restrict__ Se, const float* __restrict__ Si,
    const float* __restrict__ Ce, const float* __restrict__ Ci,
    float* __restrict__ out, int T, int nblk,
    const float* Wsyn, const float* Whist, const float* Wobs)
{
    extern __shared__ float sm[];
    const int bid = blockIdx.x;
    if (bid == 0) { prep_body(threadIdx.x, Wsyn, Whist, Wobs); return; }
    if (bid <= nblk) {
        mm_body<800, 16, 1>(Se, Ce, out, T, 0, (bid - 1) * 512, sm);
    } else {
        mm_body<200, 8, 2>(Si, Ci, out, T, 1, (bid - 1 - nblk) * 512, sm);
    }
}

// ---------------- fused sliding-window conv (known-good, unchanged) ----------------
__device__ __forceinline__ void conv_fused(unsigned long long acc2[8], float accs[8],
                                           const float2* __restrict__ sei,
                                           const float2* __restrict__ wei,
                                           const float2* __restrict__ hz,
                                           const float2* __restrict__ whz,
                                           const float* __restrict__ zo,
                                           const float* __restrict__ koh,
                                           int base_a, int base_b, int base_c) {
    unsigned long long ya[8], yb[8];
    float yc[8];
#pragma unroll
    for (int j = 0; j < 8; j++) {
        ya[j] = *(const unsigned long long*)(sei + (base_a + j) * 17);
        yb[j] = *(const unsigned long long*)(hz + (base_b + j) * 17);
        yc[j] = zo[base_c + j];
    }
#pragma unroll 1
    for (int d0 = 0; d0 < 104; d0 += 8) {
#pragma unroll
        for (int dd = 0; dd < 8; dd++) {
            unsigned long long wa = *(const unsigned long long*)(wei + d0 + dd);
            unsigned long long wb = *(const unsigned long long*)(whz + d0 + dd);
            float wc = koh[d0 + dd];
#pragma unroll
            for (int r = 0; r < 8; r++)
                asm("fma.rn.f32x2 %0, %1, %2, %0;" : "+l"(acc2[r]) : "l"(ya[(r - dd) & 7]), "l"(wa));
#pragma unroll
            for (int r = 0; r < 8; r++)
                asm("fma.rn.f32x2 %0, %1, %2, %0;" : "+l"(acc2[r]) : "l"(yb[(r - dd) & 7]), "l"(wb));
#pragma unroll
            for (int r = 0; r < 8; r++)
                accs[r] = fmaf(yc[(r - dd) & 7], wc, accs[r]);
            ya[(7 - dd) & 7] = *(const unsigned long long*)(sei + (base_a - (d0 + dd) - 1) * 17);
            yb[(7 - dd) & 7] = *(const unsigned long long*)(hz + (base_b - (d0 + dd) - 1) * 17);
            yc[(7 - dd) & 7] = zo[base_c - (d0 + dd) - 1];
        }
    }
}

// out[t,s] = exp( conv_ei + conv_hist + conv_obs + Theta[s] )
__global__ __launch_bounds__(256, 2) void conv_kernel(const float* __restrict__ Z_obs,
                                                      const float* __restrict__ Z_hid,
                                                      const float* __restrict__ Theta,
                                                      float* __restrict__ out0,
                                                      float* __restrict__ out1,
                                                      int T) {
    extern __shared__ float sm[];
    float2* sei = (float2*)sm;             // [232][17]  {syn_e, syn_i}, origin t0-104
    float2* hz  = sei + 232 * 17;          // [232][17]  {Z_hid[u], Z_obs[u+101]}, origin t0-104
    float*  zo  = (float*)(hz + 232 * 17); // [232]      Z_obs, origin t0-108
    float2* wei = (float2*)(zo + 232);     // [15][105]  {ke, ki}
    float2* whz = wei + SUB1 * 105;        // [15][105]  {kh, ko_lo}
    float*  koh = (float*)(whz + SUB1 * 105); // [15*105] ko_hi
    const int tid = threadIdx.x;
    const int t0 = blockIdx.x * 128;

    for (int li = tid; li < 232 * 16; li += 256) {
        int lt = li >> 4, s = li & 15;
        int t = t0 - 104 + lt;
        float2 v = make_float2(0.f, 0.f);
        if (s < SUB1 && t >= 0 && t < T) v = *(const float2*)(g_syn + (size_t)t * 32 + 2 * s);
        sei[lt * 17 + s] = v;
        float zh = (s < SUB1 && t >= 0 && t < T) ? Z_hid[(size_t)t * SUB1 + s] : 0.f;
        int uz = t + 101;
        float zb = (uz >= 0 && uz < T) ? Z_obs[uz] : 0.f;
        hz[lt * 17 + s] = make_float2(zh, zb);
    }
    for (int li = tid; li < 232; li += 256) {
        int t = t0 - 108 + li;
        zo[li] = (t >= 0 && t < T) ? Z_obs[t] : 0.f;
    }
    for (int li = tid; li < SUB1 * 105; li += 256) {
        wei[li] = g_wei[li];
        whz[li] = g_whz[li];
        koh[li] = g_kohi[li];
    }
    __syncthreads();

    const int s = tid & 15;
    const int trun = tid >> 4;
    if (s >= SUB1) return;   // no barriers after this point

    unsigned long long acc2[8];
#pragma unroll
    for (int r = 0; r < 8; r++) acc2[r] = 0ull;
    float accs[8];
    float th = __ldg(Theta + s);
#pragma unroll
    for (int r = 0; r < 8; r++) accs[r] = th;

    conv_fused(acc2, accs,
               sei + s, wei + s * 105,
               hz + s, whz + s * 105,
               zo, koh + s * 105,
               104 + trun * 8,    // ei:   sum_d {syn_e,syn_i}[t-d] * {ke,ki}[d]
               103 + trun * 8,    // hz:   sum_d {Z_hid[t-1-d], Z_obs[t+100-d]} * {kh,ko}[d]
               104 + trun * 8);   // obs:  sum_d Z_obs[t-4-d] * ko[104+d]

    const int tb = t0 + trun * 8;
#pragma unroll
    for (int r = 0; r < 8; r++) {
        int t = tb + r;
        if (t < T) {
            float lo, hi;
            asm("mov.b64 {%0,%1}, %2;" : "=f"(lo), "=f"(hi) : "l"(acc2[r]));
            float v = expf(lo + hi + accs[r]);
            out0[(size_t)t * SUB1 + s] = v;
            out1[(size_t)t * SUB1 + s] = v;
        }
    }
}

extern "C" void kernel_launch(void* const* d_in, const int* in_sizes, int n_in,
                              void* d_out, int out_size) {
    const float* S_e    = (const float*)d_in[0];
    const float* S_i    = (const float*)d_in[1];
    const float* Z_obs  = (const float*)d_in[2];
    const float* Z_hid  = (const float*)d_in[3];
    const float* C_e    = (const float*)d_in[4];
    const float* C_i    = (const float*)d_in[5];
    const float* W_syn  = (const float*)d_in[6];
    const float* W_hist = (const float*)d_in[7];
    const float* W_obs  = (const float*)d_in[8];
    const float* Theta  = (const float*)d_in[9];
    const int T = in_sizes[2];          // Z_obs element count

    float* out0 = (float*)d_out;
    float* out1 = (out_size >= 2 * T * SUB1) ? out0 + (size_t)T * SUB1 : out0;

    // smem: tile 2*512*16*4 + wbuf 2*8*16*8 = 67,584 (E config is the max)
    const int smem_mm = 2 * 512 * 16 * 4 + 2 * 8 * 16 * 8;
    const int smem_conv = (2 * 232 * 17 * 2 + 232 + 2 * SUB1 * 105 * 2 + SUB1 * 105) * (int)sizeof(float); // 95,532

    cudaFuncSetAttribute(mm_fused,    cudaFuncAttributeMaxDynamicSharedMemorySize, smem_mm);
    cudaFuncSetAttribute(conv_kernel, cudaFuncAttributeMaxDynamicSharedMemorySize, smem_conv);

    float* syn_ptr;
    cudaGetSymbolAddress((void**)&syn_ptr, g_syn);

    int nblk = (T + 511) / 512;
    mm_fused<<<2 * nblk + 1, 256, smem_mm>>>(S_e, S_i, C_e, C_i, syn_ptr, T, nblk,
                                             W_syn, W_hist, W_obs);

    int conv_blocks = (T + 127) / 128;
    conv_kernel<<<conv_blocks, 256, smem_conv>>>(Z_obs, Z_hid, Theta, out0, out1, T);
}

// round 15
// speedup vs baseline: 1.8361x; 1.0772x over previous
#include <cuda_runtime.h>
#include <math.h>

#define SUB1 15
#define T_MAX 120000

// ---------------- scratch (device globals — no allocs allowed) ----------------
__device__ float  g_syn[T_MAX * 32];      // interleaved {e,i} per (t,s): [t][s][2], s-pitch 32
__device__ float2 g_wei[SUB1 * 105];      // {ke[d], ki[d]}
__device__ float2 g_whz[SUB1 * 105];      // {kh[d], ko[d]}        (obs taps 0..103)
__device__ float  g_kohi[SUB1 * 105];     // ko[104+d]             (obs taps 104..207)

// ---------------- basis functions (fp32, MUFU-fast) ----------------
__device__ __forceinline__ float cos_basis_f(int b, int d) {
    const float PI_F = 3.14159265358979f;
    float raw = 5.0f * logf((float)d + 1.0f + 1e-8f);
    float phi = 1.5707963267948966f * (float)b;
    if (raw < phi - PI_F || raw > phi + PI_F) return 0.f;
    return 0.5f * cosf(raw - phi) + 0.5f;
}

__device__ __forceinline__ float obs_basis_f(int b, int x) {
    const float PI_F = 3.14159265358979f;
    float phi;
    if (b == 0) {
        phi = 0.f;
    } else if (b & 1) {           // positive-side basis (x >= 0)
        if (x < 0) return 0.f;
        phi = 1.5707963267948966f * (float)((b + 1) >> 1);
    } else {                      // negative-side basis (x <= 0)
        if (x > 0) return 0.f;
        phi = 1.5707963267948966f * (float)(b >> 1);
    }
    float r = 5.0f * logf(fabsf((float)x) + 1.0f + 1e-8f);
    if (r < phi - PI_F || r > phi + PI_F) return 0.f;
    return 0.5f * cosf(r - phi) + 0.5f;
}

// ---------------- kernel precompute, run by block 0 of the fused mm launch ----------------
__device__ void prep_body(int tid, const float* __restrict__ W_syn,
                          const float* __restrict__ W_hist,
                          const float* __restrict__ W_obs) {
    for (int idx = tid; idx < SUB1 * 105; idx += 256) {
        int s = idx / 105, d = idx % 105;
        float ke = 0.f, ki = 0.f, kh = 0.f, ko = 0.f, ko2 = 0.f;
        if (d < 100) {
            for (int b = 0; b < 13; b++) {
                float bf = cos_basis_f(b, d);
                ke = fmaf(W_syn[(s * 13 + b) * 2 + 0], bf, ke);
                ki = fmaf(W_syn[(s * 13 + b) * 2 + 1], bf, ki);
                kh = fmaf(W_hist[s * 13 + b], bf, kh);
            }
        }
        if (d < 104) {  // obs tap j = d, x = j - 100
            for (int b = 0; b < 25; b++)
                ko = fmaf(W_obs[s * 25 + b], obs_basis_f(b, d - 100), ko);
        }
        if (d <= 96) {  // obs tap j = 104 + d, x = d + 4  (j <= 200)
            for (int b = 0; b < 25; b++)
                ko2 = fmaf(W_obs[s * 25 + b], obs_basis_f(b, d + 4), ko2);
        }
        g_wei[idx]  = make_float2(ke, ki);
        g_whz[idx]  = make_float2(kh, ko);
        g_kohi[idx] = ko2;
    }
}

// ---------------- helpers ----------------
__device__ __forceinline__ unsigned smem_u32(const void* p) {
    return (unsigned)__cvta_generic_to_shared(p);
}
__device__ __forceinline__ void cp16(unsigned dst, const float* src, int sz) {
    asm volatile("cp.async.cg.shared.global [%0], [%1], 16, %2;" :: "r"(dst), "l"(src), "r"(sz));
}
__device__ __forceinline__ unsigned to_tf32(float x) {
    unsigned r;
    asm("cvt.rna.tf32.f32 %0, %1;" : "=r"(r) : "f"(x));
    return r;
}
__device__ __forceinline__ void mma_tf32(float* c, unsigned a0, unsigned a1, unsigned a2,
                                         unsigned a3, unsigned b0, unsigned b1) {
    asm volatile(
        "mma.sync.aligned.m16n8k8.row.col.f32.tf32.tf32.f32 "
        "{%0,%1,%2,%3}, {%4,%5,%6,%7}, {%8,%9}, {%0,%1,%2,%3};"
        : "+f"(c[0]), "+f"(c[1]), "+f"(c[2]), "+f"(c[3])
        : "r"(a0), "r"(a1), "r"(a2), "r"(a3), "r"(b0), "r"(b1));
}

// ---------------- tensor-core matmul: out[t*32 + 2s + ch] = sum_k S[t,k] * C[s+1,k] ----------
// tf32 mma.sync m16n8k8. 256 threads = 8 warps, 32 rows/warp, 256 rows/block.
// S streamed via cp.async double buffer; B prebuilt in per-lane fragment layout.
template <int K, int KC, int TP>
__device__ __forceinline__ void mm_tc_body(const float* __restrict__ S,
                                           const float* __restrict__ C,
                                           float* __restrict__ out, int T,
                                           int ch, int row0, float* sm) {
    const int NK8 = K / 8;      // total k8 steps
    const int CK8 = KC / 8;     // k8 steps per chunk
    const int QR = KC / 4;      // 16B quads per row per chunk
    float* tile = sm;                           // [2][256][TP]
    uint2* bfrag = (uint2*)(sm + 2 * 256 * TP); // [NK8][2 ntiles][32 lanes]
    const int tid = threadIdx.x;
    const int lane = tid & 31, wid = tid >> 5;
    const int gid = lane >> 2, tg = lane & 3;
    const unsigned tile_s = smem_u32(tile);

#define MMTC_ISSUE(c)                                                                   \
    do {                                                                                \
        const int k0_ = (c) * KC;                                                       \
        const unsigned tb_ = tile_s + (unsigned)(((c) & 1) * 256 * TP * 4);             \
        _Pragma("unroll")                                                               \
        for (int it = 0; it < QR; it++) {                                               \
            int f = it * 256 + tid;                                                     \
            int r = f / QR, q = f % QR;                                                 \
            int row = row0 + r;                                                         \
            int sz = (row < T) ? 16 : 0;                                                \
            cp16(tb_ + (unsigned)((r * TP + 4 * q) * 4),                                \
                 S + (size_t)(row < T ? row : 0) * K + k0_ + 4 * q, sz);                \
        }                                                                               \
        asm volatile("cp.async.commit_group;");                                         \
    } while (0)

    MMTC_ISSUE(0);

    // Build B fragments (overlaps with chunk-0 cp.async): bfrag[k8][nt][lane] =
    // { tf32(C[(s+1)K + k8*8 + tg]), tf32(... + tg+4) },  s = 8*nt + gid
    for (int li = tid; li < NK8 * 2 * 32; li += 256) {
        int l = li & 31, nt = (li >> 5) & 1, k8 = li >> 6;
        int s = 8 * nt + (l >> 2);
        int k = k8 * 8 + (l & 3);
        uint2 v = make_uint2(0u, 0u);
        if (s < SUB1) {
            v.x = to_tf32(__ldg(C + (size_t)(s + 1) * K + k));
            v.y = to_tf32(__ldg(C + (size_t)(s + 1) * K + k + 4));
        }
        bfrag[li] = v;
    }

    float acc[16];
#pragma unroll
    for (int i = 0; i < 16; i++) acc[i] = 0.f;

    const int nch = K / KC;
    for (int c = 0; c < nch; c++) {
        if (c + 1 < nch) {
            MMTC_ISSUE(c + 1);
            asm volatile("cp.async.wait_group 1;");
        } else {
            asm volatile("cp.async.wait_group 0;");
        }
        __syncthreads();                    // chunk c (and, on c==0, bfrag) visible
        const float* tb = tile + (c & 1) * 256 * TP;
#pragma unroll
        for (int kk = 0; kk < CK8; kk++) {
            const int k8 = c * CK8 + kk;
            const float* ap = tb + (32 * wid + gid) * TP + kk * 8 + tg;
            unsigned a0 = to_tf32(ap[0]);
            unsigned a2 = to_tf32(ap[4]);
            unsigned a1 = to_tf32(ap[8 * TP]);
            unsigned a3 = to_tf32(ap[8 * TP + 4]);
            unsigned a4 = to_tf32(ap[16 * TP]);
            unsigned a6 = to_tf32(ap[16 * TP + 4]);
            unsigned a5 = to_tf32(ap[24 * TP]);
            unsigned a7 = to_tf32(ap[24 * TP + 4]);
            uint2 b0 = bfrag[(k8 * 2 + 0) * 32 + lane];
            uint2 b1 = bfrag[(k8 * 2 + 1) * 32 + lane];
            mma_tf32(acc + 0,  a0, a1, a2, a3, b0.x, b0.y);   // mtile0, ntile0
            mma_tf32(acc + 4,  a0, a1, a2, a3, b1.x, b1.y);   // mtile0, ntile1
            mma_tf32(acc + 8,  a4, a5, a6, a7, b0.x, b0.y);   // mtile1, ntile0
            mma_tf32(acc + 12, a4, a5, a6, a7, b1.x, b1.y);   // mtile1, ntile1
        }
        __syncthreads();
    }
#undef MMTC_ISSUE

    // store: c0=(row gid, col 2tg), c1=+1col, c2=(row gid+8), c3 both
    const int tbase = row0 + 32 * wid + gid;
#pragma unroll
    for (int mt = 0; mt < 2; mt++) {
#pragma unroll
        for (int nt = 0; nt < 2; nt++) {
            const float* a = acc + (mt * 2 + nt) * 4;
            int s0 = 8 * nt + 2 * tg;
            int t0 = tbase + 16 * mt;
            if (t0 < T) {
                out[(size_t)t0 * 32 + 2 * s0 + ch] = a[0];
                if (s0 + 1 < SUB1) out[(size_t)t0 * 32 + 2 * (s0 + 1) + ch] = a[1];
            }
            int t1 = t0 + 8;
            if (t1 < T) {
                out[(size_t)t1 * 32 + 2 * s0 + ch] = a[2];
                if (s0 + 1 < SUB1) out[(size_t)t1 * 32 + 2 * (s0 + 1) + ch] = a[3];
            }
        }
    }
}

// Fused launch: block 0 = prep, blocks [1, nblk] = E matmul, rest = I matmul.
__global__ __launch_bounds__(256, 2) void mm_fused(
    const float* __restrict__ Se, const float* __restrict__ Si,
    const float* __restrict__ Ce, const float* __restrict__ Ci,
    float* __restrict__ out, int T, int nblk,
    const float* Wsyn, const float* Whist, const float* Wobs)
{
    extern __shared__ float sm[];
    const int bid = blockIdx.x;
    if (bid == 0) { prep_body(threadIdx.x, Wsyn, Whist, Wobs); return; }
    if (bid <= nblk) {
        mm_tc_body<800, 16, 20>(Se, Ce, out, T, 0, (bid - 1) * 256, sm);
    } else {
        mm_tc_body<200, 8, 12>(Si, Ci, out, T, 1, (bid - 1 - nblk) * 256, sm);
    }
}

// ---------------- fused sliding-window conv (known-good, unchanged) ----------------
__device__ __forceinline__ void conv_fused(unsigned long long acc2[8], float accs[8],
                                           const float2* __restrict__ sei,
                                           const float2* __restrict__ wei,
                                           const float2* __restrict__ hz,
                                           const float2* __restrict__ whz,
                                           const float* __restrict__ zo,
                                           const float* __restrict__ koh,
                                           int base_a, int base_b, int base_c) {
    unsigned long long ya[8], yb[8];
    float yc[8];
#pragma unroll
    for (int j = 0; j < 8; j++) {
        ya[j] = *(const unsigned long long*)(sei + (base_a + j) * 17);
        yb[j] = *(const unsigned long long*)(hz + (base_b + j) * 17);
        yc[j] = zo[base_c + j];
    }
#pragma unroll 1
    for (int d0 = 0; d0 < 104; d0 += 8) {
#pragma unroll
        for (int dd = 0; dd < 8; dd++) {
            unsigned long long wa = *(const unsigned long long*)(wei + d0 + dd);
            unsigned long long wb = *(const unsigned long long*)(whz + d0 + dd);
            float wc = koh[d0 + dd];
#pragma unroll
            for (int r = 0; r < 8; r++)
                asm("fma.rn.f32x2 %0, %1, %2, %0;" : "+l"(acc2[r]) : "l"(ya[(r - dd) & 7]), "l"(wa));
#pragma unroll
            for (int r = 0; r < 8; r++)
                asm("fma.rn.f32x2 %0, %1, %2, %0;" : "+l"(acc2[r]) : "l"(yb[(r - dd) & 7]), "l"(wb));
#pragma unroll
            for (int r = 0; r < 8; r++)
                accs[r] = fmaf(yc[(r - dd) & 7], wc, accs[r]);
            ya[(7 - dd) & 7] = *(const unsigned long long*)(sei + (base_a - (d0 + dd) - 1) * 17);
            yb[(7 - dd) & 7] = *(const unsigned long long*)(hz + (base_b - (d0 + dd) - 1) * 17);
            yc[(7 - dd) & 7] = zo[base_c - (d0 + dd) - 1];
        }
    }
}

// out[t,s] = exp( conv_ei + conv_hist + conv_obs + Theta[s] )
__global__ __launch_bounds__(256, 2) void conv_kernel(const float* __restrict__ Z_obs,
                                                      const float* __restrict__ Z_hid,
                                                      const float* __restrict__ Theta,
                                                      float* __restrict__ out0,
                                                      float* __restrict__ out1,
                                                      int T) {
    extern __shared__ float sm[];
    float2* sei = (float2*)sm;             // [232][17]  {syn_e, syn_i}, origin t0-104
    float2* hz  = sei + 232 * 17;          // [232][17]  {Z_hid[u], Z_obs[u+101]}, origin t0-104
    float*  zo  = (float*)(hz + 232 * 17); // [232]      Z_obs, origin t0-108
    float2* wei = (float2*)(zo + 232);     // [15][105]  {ke, ki}
    float2* whz = wei + SUB1 * 105;        // [15][105]  {kh, ko_lo}
    float*  koh = (float*)(whz + SUB1 * 105); // [15*105] ko_hi
    const int tid = threadIdx.x;
    const int t0 = blockIdx.x * 128;

    for (int li = tid; li < 232 * 16; li += 256) {
        int lt = li >> 4, s = li & 15;
        int t = t0 - 104 + lt;
        float2 v = make_float2(0.f, 0.f);
        if (s < SUB1 && t >= 0 && t < T) v = *(const float2*)(g_syn + (size_t)t * 32 + 2 * s);
        sei[lt * 17 + s] = v;
        float zh = (s < SUB1 && t >= 0 && t < T) ? Z_hid[(size_t)t * SUB1 + s] : 0.f;
        int uz = t + 101;
        float zb = (uz >= 0 && uz < T) ? Z_obs[uz] : 0.f;
        hz[lt * 17 + s] = make_float2(zh, zb);
    }
    for (int li = tid; li < 232; li += 256) {
        int t = t0 - 108 + li;
        zo[li] = (t >= 0 && t < T) ? Z_obs[t] : 0.f;
    }
    for (int li = tid; li < SUB1 * 105; li += 256) {
        wei[li] = g_wei[li];
        whz[li] = g_whz[li];
        koh[li] = g_kohi[li];
    }
    __syncthreads();

    const int s = tid & 15;
    const int trun = tid >> 4;
    if (s >= SUB1) return;   // no barriers after this point

    unsigned long long acc2[8];
#pragma unroll
    for (int r = 0; r < 8; r++) acc2[r] = 0ull;
    float accs[8];
    float th = __ldg(Theta + s);
#pragma unroll
    for (int r = 0; r < 8; r++) accs[r] = th;

    conv_fused(acc2, accs,
               sei + s, wei + s * 105,
               hz + s, whz + s * 105,
               zo, koh + s * 105,
               104 + trun * 8,    // ei:   sum_d {syn_e,syn_i}[t-d] * {ke,ki}[d]
               103 + trun * 8,    // hz:   sum_d {Z_hid[t-1-d], Z_obs[t+100-d]} * {kh,ko}[d]
               104 + trun * 8);   // obs:  sum_d Z_obs[t-4-d] * ko[104+d]

    const int tb = t0 + trun * 8;
#pragma unroll
    for (int r = 0; r < 8; r++) {
        int t = tb + r;
        if (t < T) {
            float lo, hi;
            asm("mov.b64 {%0,%1}, %2;" : "=f"(lo), "=f"(hi) : "l"(acc2[r]));
            float v = expf(lo + hi + accs[r]);
            out0[(size_t)t * SUB1 + s] = v;
            out1[(size_t)t * SUB1 + s] = v;
        }
    }
}

extern "C" void kernel_launch(void* const* d_in, const int* in_sizes, int n_in,
                              void* d_out, int out_size) {
    const float* S_e    = (const float*)d_in[0];
    const float* S_i    = (const float*)d_in[1];
    const float* Z_obs  = (const float*)d_in[2];
    const float* Z_hid  = (const float*)d_in[3];
    const float* C_e    = (const float*)d_in[4];
    const float* C_i    = (const float*)d_in[5];
    const float* W_syn  = (const float*)d_in[6];
    const float* W_hist = (const float*)d_in[7];
    const float* W_obs  = (const float*)d_in[8];
    const float* Theta  = (const float*)d_in[9];
    const int T = in_sizes[2];          // Z_obs element count

    float* out0 = (float*)d_out;
    float* out1 = (out_size >= 2 * T * SUB1) ? out0 + (size_t)T * SUB1 : out0;

    // mm smem (E config is max): tile 2*256*20*4 = 40,960 + bfrag 100*2*32*8 = 51,200
    const int smem_mm = 2 * 256 * 20 * 4 + 100 * 2 * 32 * 8;   // 92,160
    const int smem_conv = (2 * 232 * 17 * 2 + 232 + 2 * SUB1 * 105 * 2 + SUB1 * 105) * (int)sizeof(float); // 95,532

    cudaFuncSetAttribute(mm_fused,    cudaFuncAttributeMaxDynamicSharedMemorySize, smem_mm);
    cudaFuncSetAttribute(conv_kernel, cudaFuncAttributeMaxDynamicSharedMemorySize, smem_conv);

    float* syn_ptr;
    cudaGetSymbolAddress((void**)&syn_ptr, g_syn);

    int nblk = (T + 255) / 256;
    mm_fused<<<2 * nblk + 1, 256, smem_mm>>>(S_e, S_i, C_e, C_i, syn_ptr, T, nblk,
                                             W_syn, W_hist, W_obs);

    int conv_blocks = (T + 127) / 128;
    conv_kernel<<<conv_blocks, 256, smem_conv>>>(Z_obs, Z_hid, Theta, out0, out1, T);
}